// round 13
// baseline (speedup 1.0000x reference)
#include <cuda_runtime.h>
#include <cuda_fp16.h>

typedef unsigned long long u64;

// ---------------------------------------------------------------------------
// packed f32x2 helpers (Blackwell FFMA2 path)
// ---------------------------------------------------------------------------
__device__ __forceinline__ u64 ffma2(u64 a, u64 b, u64 c) {
    u64 d; asm("fma.rn.f32x2 %0, %1, %2, %3;" : "=l"(d) : "l"(a), "l"(b), "l"(c)); return d;
}
__device__ __forceinline__ u64 fadd2(u64 a, u64 b) {
    u64 d; asm("add.rn.f32x2 %0, %1, %2;" : "=l"(d) : "l"(a), "l"(b)); return d;
}
__device__ __forceinline__ u64 fmul2(u64 a, u64 b) {
    u64 d; asm("mul.rn.f32x2 %0, %1, %2;" : "=l"(d) : "l"(a), "l"(b)); return d;
}
__device__ __forceinline__ u64 pack2(float lo, float hi) {
    u64 d; asm("mov.b64 %0, {%1, %2};" : "=l"(d) : "f"(lo), "f"(hi)); return d;
}
__device__ __forceinline__ float2 unpk(u64 v) {
    float2 r; asm("mov.b64 {%0, %1}, %2;" : "=f"(r.x), "=f"(r.y) : "l"(v)); return r;
}
__device__ __forceinline__ u64 dup2(float c) { return pack2(c, c); }

// fp16x2 weight -> packed f32x2 (2x F2F.F32.F16 + reg pairing)
__device__ __forceinline__ u64 h2u(unsigned hw) {
    float lo, hi;
    asm("cvt.f32.f16 %0, %1;" : "=f"(lo) : "h"((unsigned short)(hw & 0xffffu)));
    asm("cvt.f32.f16 %0, %1;" : "=f"(hi) : "h"((unsigned short)(hw >> 16)));
    return pack2(lo, hi);
}

// ---------------------------------------------------------------------------
// Tsit5 constants
// ---------------------------------------------------------------------------
#define A21f 0.161f
#define A31f (-0.008480655492356989f)
#define A32f 0.335480655492357f
#define A41f 2.8971530571054935f
#define A42f (-6.359448489975075f)
#define A43f 4.3622954328695815f
#define A51f 5.325864828439257f
#define A52f (-11.748883564062828f)
#define A53f 7.4955393428898365f
#define A54f (-0.09249506636175525f)
#define A61f 5.86145544294642f
#define A62f (-12.92096931784711f)
#define A63f 8.159367898576159f
#define A64f (-0.071584973281401f)
#define A65f (-0.028269050394068383f)
#define B1f 0.09646076681806523f
#define B2f 0.01f
#define B3f 0.4798896504144996f
#define B4f 1.379008574103742f
#define B5f (-3.290069515436081f)
#define B6f 2.324710524099774f
#define E1f (-0.00178001105222577714f)
#define E2f (-0.0008164344596567469f)
#define E3f 0.007880878010261995f
#define E4f (-0.1447110071732629f)
#define E5f 0.5823571654525552f
#define E6f (-0.45808210592918697f)
#define E7f 0.015151515151515152f

#define RTOLf 1e-3f
#define ATOLf 1e-6f
#define DT0f  1e-3f

#define DDIM 64
#define HID  32
#define TRAJ_LEN 11
#define N_INTERVALS 10
#define MAX_INNER 64

#define WARPS_PER_BLOCK 4
#define THREADS_PER_BLOCK (WARPS_PER_BLOCK * 32)
#define PERSISTENT_BLOCKS 456   // 3 blocks/SM x 152 SMs (GB300)

// global work-stealing counter (reset by init kernel every launch)
__device__ int g_sys_counter;

// fast softplus: max(x,0) + log(1 + exp(-|x|)) with MUFU exp/log
__device__ __forceinline__ float softplus_f(float x) {
    return fmaxf(x, 0.0f) + __logf(1.0f + __expf(-fabsf(x)));
}

__global__ void __launch_bounds__(THREADS_PER_BLOCK, 3)
neural_ode_kernel(const float* __restrict__ x0s,
                  const float* __restrict__ W1, const float* __restrict__ b1,
                  const float* __restrict__ W2, const float* __restrict__ b2,
                  const float* __restrict__ W3, const float* __restrict__ b3,
                  const int* __restrict__ Tptr,
                  float* __restrict__ out, int B, int nIdx)
{
    const int lane = threadIdx.x & 31;
    const int wrp  = threadIdx.x >> 5;

    const int q  = lane >> 3;    // input quarter (0..3) for L1
    const int mq = lane & 7;     // L1 unit base: units {mq, mq+8, mq+16, mq+24}
    const int g  = lane >> 4;    // input half (0/1) for L2/L3
    const int m16 = lane & 15;   // L2 units {m16, m16+16}; L3 rows {m16+16j}

    __shared__ __align__(16) float sv [WARPS_PER_BLOCK][DDIM]; // stage vector z
    __shared__ __align__(16) float sh1[WARPS_PER_BLOCK][HID];  // hidden 1
    __shared__ __align__(16) float sh2[WARPS_PER_BLOCK][HID];  // hidden 2

    float* svw  = sv [wrp];
    float* sh1w = sh1[wrp];
    float* sh2w = sh2[wrp];

    // ---- weights into registers, ONCE per persistent warp ----
    // L1 (fp16 storage): 4 units x quarter-input (16 floats) = 32 half2 regs
    unsigned w1h[32];
    #pragma unroll
    for (int j = 0; j < 4; ++j) {
        const int u = mq + 8 * j;
        const float2* r = (const float2*)(W1 + u * DDIM + 16 * q);
        #pragma unroll
        for (int k = 0; k < 8; ++k) {
            float2 v = r[k];
            __half2 h = __floats2half2_rn(v.x, v.y);
            w1h[j * 8 + k] = *(unsigned*)&h;
        }
    }
    // L2 (f32): 2 units x half-input (16 floats) = 16 u64
    u64 w2u[16];
    #pragma unroll
    for (int j = 0; j < 2; ++j) {
        const int u = m16 + 16 * j;
        const float2* r = (const float2*)(W2 + u * HID + 16 * g);
        #pragma unroll
        for (int k = 0; k < 8; ++k) { float2 v = r[k]; w2u[j * 8 + k] = pack2(v.x, v.y); }
    }
    // L3 (fp16 storage): 4 rows {m16+16j} x half-input (16 floats) = 32 half2 regs
    unsigned w3h[32];
    #pragma unroll
    for (int j = 0; j < 4; ++j) {
        const int row = m16 + 16 * j;
        const float2* r = (const float2*)(W3 + row * HID + 16 * g);
        #pragma unroll
        for (int k = 0; k < 8; ++k) {
            float2 v = r[k];
            __half2 h = __floats2half2_rn(v.x, v.y);
            w3h[j * 8 + k] = *(unsigned*)&h;
        }
    }
    const float b1r = b1[lane];
    const float b2r = b2[lane];
    const u64 b3p = pack2(b3[lane], b3[lane + 32]);

    const float Tf    = (float)(*Tptr);
    const float stepT = Tf / (float)N_INTERVALS;

    // f(z) -> k; z/k packed as coords (lane, lane+32)
    auto evalf = [&](u64 z) -> u64 {
        float2 zz = unpk(z);
        svw[lane]      = zz.x;    // STS.32
        svw[lane + 32] = zz.y;    // STS.32
        __syncwarp();
        // ---- L1 quarter-split: 4 LDS.128, 32 FFMA2 (+cvt), 2 shfl rounds ----
        u64 a0 = 0, a1 = 0, a2 = 0, a3 = 0;
        const ulonglong2* vv = (const ulonglong2*)svw;
        #pragma unroll
        for (int c = 0; c < 4; ++c) {
            ulonglong2 ch = vv[4 * q + c];
            a0 = ffma2(h2u(w1h[2 * c]),      ch.x, a0);
            a1 = ffma2(h2u(w1h[8 + 2 * c]),  ch.x, a1);
            a2 = ffma2(h2u(w1h[16 + 2 * c]), ch.x, a2);
            a3 = ffma2(h2u(w1h[24 + 2 * c]), ch.x, a3);
            a0 = ffma2(h2u(w1h[2 * c + 1]),      ch.y, a0);
            a1 = ffma2(h2u(w1h[8 + 2 * c + 1]),  ch.y, a1);
            a2 = ffma2(h2u(w1h[16 + 2 * c + 1]), ch.y, a2);
            a3 = ffma2(h2u(w1h[24 + 2 * c + 1]), ch.y, a3);
        }
        float2 f0 = unpk(a0), f1 = unpk(a1), f2 = unpk(a2), f3 = unpk(a3);
        u64 P = pack2(f0.x + f0.y, f1.x + f1.y);   // units (mq, mq+8)
        u64 Q = pack2(f2.x + f2.y, f3.x + f3.y);   // units (mq+16, mq+24)
        P = fadd2(P, __shfl_xor_sync(0xffffffffu, P, 8));
        Q = fadd2(Q, __shfl_xor_sync(0xffffffffu, Q, 8));
        P = fadd2(P, __shfl_xor_sync(0xffffffffu, P, 16));
        Q = fadd2(Q, __shfl_xor_sync(0xffffffffu, Q, 16));
        float2 Pv = unpk(P), Qv = unpk(Q);
        // unit this lane stores: mq + 8*q == lane
        float pre1 = (q == 0) ? Pv.x : (q == 1) ? Pv.y : (q == 2) ? Qv.x : Qv.y;
        sh1w[lane] = softplus_f(pre1 + b1r);   // STS.32 to h1[lane]
        __syncwarp();
        // ---- L2 half-split (f32 weights): 4 LDS.128, 16 FFMA2, 1 shfl ----
        u64 cA = 0, cB = 0;
        const ulonglong2* hh = (const ulonglong2*)sh1w;
        #pragma unroll
        for (int c = 0; c < 4; ++c) {
            ulonglong2 ch = hh[4 * g + c];
            cA = ffma2(w2u[2 * c],     ch.x, cA);
            cB = ffma2(w2u[8 + 2 * c], ch.x, cB);
            cA = ffma2(w2u[2 * c + 1],     ch.y, cA);
            cB = ffma2(w2u[8 + 2 * c + 1], ch.y, cB);
        }
        float2 fa = unpk(cA), fb = unpk(cB);
        u64 R = pack2(fa.x + fa.y, fb.x + fb.y);   // units (m16, m16+16)
        R = fadd2(R, __shfl_xor_sync(0xffffffffu, R, 16));
        float2 Rv = unpk(R);
        float pre2 = (g == 0) ? Rv.x : Rv.y;       // unit m16+16g == lane
        sh2w[lane] = softplus_f(pre2 + b2r);       // STS.32 to h2[lane]
        __syncwarp();
        // ---- L3 half-split: 4 LDS.128, 32 FFMA2 (+cvt), 1 shfl, free placement ----
        u64 e0 = 0, e1 = 0, e2 = 0, e3 = 0;  // rows m16, m16+16, m16+32, m16+48
        const ulonglong2* gg = (const ulonglong2*)sh2w;
        #pragma unroll
        for (int c = 0; c < 4; ++c) {
            ulonglong2 ch = gg[4 * g + c];
            e0 = ffma2(h2u(w3h[2 * c]),      ch.x, e0);
            e1 = ffma2(h2u(w3h[8 + 2 * c]),  ch.x, e1);
            e2 = ffma2(h2u(w3h[16 + 2 * c]), ch.x, e2);
            e3 = ffma2(h2u(w3h[24 + 2 * c]), ch.x, e3);
            e0 = ffma2(h2u(w3h[2 * c + 1]),      ch.y, e0);
            e1 = ffma2(h2u(w3h[8 + 2 * c + 1]),  ch.y, e1);
            e2 = ffma2(h2u(w3h[16 + 2 * c + 1]), ch.y, e2);
            e3 = ffma2(h2u(w3h[24 + 2 * c + 1]), ch.y, e3);
        }
        float2 s0 = unpk(e0), s1 = unpk(e1), s2 = unpk(e2), s3 = unpk(e3);
        u64 P3 = pack2(s0.x + s0.y, s2.x + s2.y);  // rows (m16, m16+32)
        u64 Q3 = pack2(s1.x + s1.y, s3.x + s3.y);  // rows (m16+16, m16+48)
        P3 = fadd2(P3, __shfl_xor_sync(0xffffffffu, P3, 16));
        Q3 = fadd2(Q3, __shfl_xor_sync(0xffffffffu, Q3, 16));
        // lane needs rows (lane, lane+32): g==0 -> P3, g==1 -> Q3. no traffic.
        u64 kv = (g == 0) ? P3 : Q3;
        // no trailing syncwarp: next call's barriers cover the WAR hazards
        return fadd2(kv, b3p);
    };

    // =======================================================================
    // persistent loop: steal system IDs until exhausted
    // =======================================================================
    for (;;) {
        int sys;
        if (lane == 0) sys = atomicAdd(&g_sys_counter, 1);
        sys = __shfl_sync(0xffffffffu, sys, 0);
        if (sys >= B) break;

        // state: coords (lane, lane+32)
        float ylo = x0s[sys * DDIM + lane];
        float yhi = x0s[sys * DDIM + 32 + lane];
        u64 yp = pack2(ylo, yhi);

        const int trajBase = sys * (TRAJ_LEN * DDIM);
        out[trajBase + lane]      = ylo;   // ts[0] row
        out[trajBase + 32 + lane] = yhi;

        float t = 0.0f;
        float dt = DT0f;
        int   n  = 0;

        u64 k1p = evalf(yp);   // FSAL seed

        for (int iv = 1; iv <= N_INTERVALS; ++iv) {
            const float t_target = (iv == N_INTERVALS) ? Tf : stepT * (float)iv;

            for (int it = 0; it < MAX_INNER; ++it) {
                float remaining = t_target - t;
                if (remaining <= 1e-12f) break;
                float h = fminf(dt, fmaxf(remaining, 0.0f));
                u64 hp = dup2(h);

                // stage 2
                u64 s = fmul2(dup2(A21f), k1p);
                u64 k2p = evalf(ffma2(hp, s, yp));
                // stage 3
                s = ffma2(dup2(A32f), k2p, fmul2(dup2(A31f), k1p));
                u64 k3p = evalf(ffma2(hp, s, yp));
                // stage 4
                s = ffma2(dup2(A42f), k2p, fmul2(dup2(A41f), k1p));
                s = ffma2(dup2(A43f), k3p, s);
                u64 k4p = evalf(ffma2(hp, s, yp));
                // stage 5
                s = ffma2(dup2(A52f), k2p, fmul2(dup2(A51f), k1p));
                s = ffma2(dup2(A53f), k3p, s);
                s = ffma2(dup2(A54f), k4p, s);
                u64 k5p = evalf(ffma2(hp, s, yp));
                // stage 6
                s = ffma2(dup2(A62f), k2p, fmul2(dup2(A61f), k1p));
                s = ffma2(dup2(A63f), k3p, s);
                s = ffma2(dup2(A64f), k4p, s);
                s = ffma2(dup2(A65f), k5p, s);
                u64 k6p = evalf(ffma2(hp, s, yp));
                // y5
                s = ffma2(dup2(B2f), k2p, fmul2(dup2(B1f), k1p));
                s = ffma2(dup2(B3f), k3p, s);
                s = ffma2(dup2(B4f), k4p, s);
                s = ffma2(dup2(B5f), k5p, s);
                s = ffma2(dup2(B6f), k6p, s);
                u64 y5p = ffma2(hp, s, yp);
                // stage 7 (FSAL)
                u64 k7p = evalf(y5p);
                // error estimate
                s = ffma2(dup2(E2f), k2p, fmul2(dup2(E1f), k1p));
                s = ffma2(dup2(E3f), k3p, s);
                s = ffma2(dup2(E4f), k4p, s);
                s = ffma2(dup2(E5f), k5p, s);
                s = ffma2(dup2(E6f), k6p, s);
                s = ffma2(dup2(E7f), k7p, s);
                float2 ev  = unpk(fmul2(hp, s));
                float2 yv  = unpk(yp);
                float2 y5v = unpk(y5p);

                float scl = fmaf(RTOLf, fmaxf(fabsf(yv.x), fabsf(y5v.x)), ATOLf);
                float sch = fmaf(RTOLf, fmaxf(fabsf(yv.y), fabsf(y5v.y)), ATOLf);
                float ql = __fdividef(ev.x, scl);
                float qh = __fdividef(ev.y, sch);
                float local = ql * ql + qh * qh;
                #pragma unroll
                for (int o = 16; o > 0; o >>= 1)
                    local += __shfl_xor_sync(0xffffffffu, local, o);

                // accept <=> local <= 64; fac = 0.9*exp2(-0.1*(log2(local)-6))
                bool accept = (local <= 64.0f);
                float lg = __log2f(fmaxf(local, 4.096e-18f)) - 6.0f;
                float fac = 0.9f * exp2f(-0.1f * lg);
                fac = fminf(fmaxf(fac, 0.1f), 5.0f);

                if (accept) {
                    t = t + h;
                    yp  = y5p;
                    k1p = k7p;   // FSAL
                }
                dt = fmaxf(h * fac, 1e-8f);
                n += 1;
            }

            float2 yv = unpk(yp);
            out[trajBase + iv * DDIM + lane]      = yv.x;
            out[trajBase + iv * DDIM + 32 + lane] = yv.y;
        }

        if (lane == 0)
            atomicAdd(&out[nIdx], (float)n);   // integer-valued, exact
    }
}

// zero the poisoned tail of the output buffer AND the work-stealing counter
__global__ void init_kernel(float* __restrict__ out, int start, int total) {
    if (blockIdx.x == 0 && threadIdx.x == 0) g_sys_counter = 0;
    int i = start + blockIdx.x * blockDim.x + threadIdx.x;
    if (i < total) out[i] = 0.0f;
}

extern "C" void kernel_launch(void* const* d_in, const int* in_sizes, int n_in,
                              void* d_out, int out_size) {
    const float* x0s = (const float*)d_in[0];
    const float* W1  = (const float*)d_in[1];
    const float* b1  = (const float*)d_in[2];
    const float* W2  = (const float*)d_in[3];
    const float* b2  = (const float*)d_in[4];
    const float* W3  = (const float*)d_in[5];
    const float* b3  = (const float*)d_in[6];
    const int*   Tp  = (const int*)d_in[7];

    const int B = in_sizes[0] / DDIM;
    float* out = (float*)d_out;

    int trajElems = B * TRAJ_LEN * DDIM;
    if (trajElems >= out_size) trajElems = out_size - 1;  // safety
    const int nIdx = trajElems;

    const int tail = out_size - trajElems;
    int initBlocks = (tail + 255) / 256; if (initBlocks < 1) initBlocks = 1;
    init_kernel<<<initBlocks, 256>>>(out, trajElems, out_size);

    neural_ode_kernel<<<PERSISTENT_BLOCKS, THREADS_PER_BLOCK>>>(
        x0s, W1, b1, W2, b2, W3, b3, Tp, out, B, nIdx);
}